// round 2
// baseline (speedup 1.0000x reference)
#include <cuda_runtime.h>
#include <math.h>

#define K_CODES 50257
#define D 144
#define CHUNKS 36            // D / 4
#define NROWS 4096
#define TM 32                // rows per CTA
#define TN 128               // codes per smem tile
#define EPITCH 40            // padded float4-chunks per e row (mult of 8 for swizzle)
#define ZPITCH 37            // float4-chunks per z row (148 floats, 16B aligned)
#define NSPLIT 16
#define NTILES ((K_CODES + TN - 1) / TN)   // 393
#define NZQ (NROWS * D)                     // 589824
#define NPART (NZQ / 256)                   // 2304

__device__ unsigned long long g_best[NROWS];
__device__ float g_esq[K_CODES];
__device__ float g_partials[NPART];

// ---------------------------------------------------------------------------
// Kernel 0: init per-row argmin keys
// ---------------------------------------------------------------------------
__global__ void vq_init_best() {
    int i = blockIdx.x * blockDim.x + threadIdx.x;
    if (i < NROWS) g_best[i] = 0xFFFFFFFFFFFFFFFFull;
}

// ---------------------------------------------------------------------------
// Kernel 1: esq[k] = sum_d emb[k][d]^2   (one warp per code)
// ---------------------------------------------------------------------------
__global__ void vq_esq(const float* __restrict__ emb) {
    int warp = (blockIdx.x * blockDim.x + threadIdx.x) >> 5;
    int lane = threadIdx.x & 31;
    if (warp >= K_CODES) return;
    const float* row = emb + (size_t)warp * D;
    float s = 0.f;
    for (int d = lane; d < D; d += 32) {
        float v = row[d];
        s = fmaf(v, v, s);
    }
#pragma unroll
    for (int off = 16; off; off >>= 1)
        s += __shfl_xor_sync(0xffffffffu, s, off);
    if (lane == 0) g_esq[warp] = s;
}

// ---------------------------------------------------------------------------
// Kernel 2: main distance + argmin
//   128 threads: warp = row-group (8 rows), lane = code-thread (4 codes)
// ---------------------------------------------------------------------------
__global__ void __launch_bounds__(128) vq_main(const float* __restrict__ z,
                                               const float* __restrict__ emb) {
    extern __shared__ float sm[];
    float4* zs4  = (float4*)sm;                        // [TM][ZPITCH]
    float4* es4  = zs4 + TM * ZPITCH;                  // [TN][EPITCH]
    float*  essq = (float*)(es4 + TN * EPITCH);        // [TN]
    float*  rowsq = essq + TN;                         // [TM]

    const int tid = threadIdx.x;
    const int ct  = tid & 31;   // lane: code-thread
    const int rt  = tid >> 5;   // warp: row-group
    const int rowBase = blockIdx.x * TM;

    // Load z tile (32 x 144 floats) as float4
    for (int f = tid; f < TM * CHUNKS; f += 128) {
        int r = f / CHUNKS, dc = f % CHUNKS;
        zs4[r * ZPITCH + dc] =
            ((const float4*)z)[(size_t)(rowBase + r) * CHUNKS + dc];
    }
    __syncthreads();

    // rowsq: sequential fp32 sum per row (mirrors reference reduction style)
    if (tid < TM) {
        const float* zr = (const float*)&zs4[tid * ZPITCH];
        float s = 0.f;
        for (int d = 0; d < D; d++) s = fmaf(zr[d], zr[d], s);
        rowsq[tid] = s;
    }

    float bestV[8];
    int   bestI[8];
#pragma unroll
    for (int r = 0; r < 8; r++) { bestV[r] = INFINITY; bestI[r] = 0; }

    const int tilesPerSplit = (NTILES + NSPLIT - 1) / NSPLIT;
    int tbeg = blockIdx.y * tilesPerSplit;
    int tend = tbeg + tilesPerSplit;
    if (tend > NTILES) tend = NTILES;

    for (int t = tbeg; t < tend; t++) {
        const int cb = t * TN;
        __syncthreads();   // protect es from previous tile's readers

        // Load e tile (128 codes x 36 chunks), XOR-swizzled
        for (int f = tid; f < TN * CHUNKS; f += 128) {
            int c = f / CHUNKS, dc = f % CHUNKS;
            int cg = cb + c;
            float4 v = make_float4(0.f, 0.f, 0.f, 0.f);
            if (cg < K_CODES)
                v = ((const float4*)emb)[(size_t)cg * CHUNKS + dc];
            es4[c * EPITCH + (dc ^ ((c >> 2) & 7))] = v;
        }
        if (tid < TN) {
            int cg = cb + tid;
            essq[tid] = (cg < K_CODES) ? g_esq[cg] : INFINITY;
        }
        __syncthreads();

        float acc[8][4];
#pragma unroll
        for (int r = 0; r < 8; r++)
#pragma unroll
            for (int j = 0; j < 4; j++) acc[r][j] = 0.f;

#pragma unroll 2
        for (int dc = 0; dc < CHUNKS; dc++) {
            float4 ev[4];
#pragma unroll
            for (int j = 0; j < 4; j++) {
                int c = ct * 4 + j;
                ev[j] = es4[c * EPITCH + (dc ^ ((c >> 2) & 7))];
            }
#pragma unroll
            for (int r = 0; r < 8; r++) {
                float4 zv = zs4[(rt * 8 + r) * ZPITCH + dc];
#pragma unroll
                for (int j = 0; j < 4; j++) {
                    acc[r][j] = fmaf(zv.x, ev[j].x, acc[r][j]);
                    acc[r][j] = fmaf(zv.y, ev[j].y, acc[r][j]);
                    acc[r][j] = fmaf(zv.z, ev[j].z, acc[r][j]);
                    acc[r][j] = fmaf(zv.w, ev[j].w, acc[r][j]);
                }
            }
        }

        // Epilogue: d = (rowsq + esq) - 2*dot  (2*dot exact -> FMA-safe)
#pragma unroll
        for (int r = 0; r < 8; r++) {
            float rs = rowsq[rt * 8 + r];
#pragma unroll
            for (int j = 0; j < 4; j++) {
                int c = ct * 4 + j;
                float d = (rs + essq[c]) - 2.0f * acc[r][j];
                if (d < bestV[r]) { bestV[r] = d; bestI[r] = cb + c; }
            }
        }
    }

    // Warp-reduce each row-group's best, tie -> smaller index via packed key
#pragma unroll
    for (int r = 0; r < 8; r++) {
        unsigned long long key =
            (((unsigned long long)__float_as_uint(bestV[r])) << 32) |
            (unsigned)bestI[r];
#pragma unroll
        for (int off = 16; off; off >>= 1) {
            unsigned long long o = __shfl_xor_sync(0xffffffffu, key, off);
            key = (o < key) ? o : key;
        }
        if (ct == 0) atomicMin(&g_best[rowBase + rt * 8 + r], key);
    }
}

// ---------------------------------------------------------------------------
// Kernel 3: gather z_q, write indices, per-block loss partials
// ---------------------------------------------------------------------------
__global__ void vq_gather(const float* __restrict__ z,
                          const float* __restrict__ emb,
                          float* __restrict__ out, int out_size) {
    __shared__ float red[256];
    int i = blockIdx.x * 256 + threadIdx.x;
    float dsq = 0.f;
    if (i < NZQ) {
        int row = i / D;
        int col = i - row * D;
        unsigned idx = (unsigned)(g_best[row] & 0xffffffffull);
        float q = emb[(size_t)idx * D + col];
        out[i] = q;
        float df = q - z[i];
        dsq = df * df;
        if (col == 0 && out_size >= NZQ + NROWS)
            out[NZQ + row] = (float)idx;
    }
    red[threadIdx.x] = dsq;
    __syncthreads();
#pragma unroll
    for (int s = 128; s; s >>= 1) {
        if (threadIdx.x < s) red[threadIdx.x] += red[threadIdx.x + s];
        __syncthreads();
    }
    if (threadIdx.x == 0) g_partials[blockIdx.x] = red[0];
}

// ---------------------------------------------------------------------------
// Kernel 4: final deterministic loss reduction
// ---------------------------------------------------------------------------
__global__ void vq_loss(float* __restrict__ out, int out_size) {
    __shared__ float red[256];
    float s = 0.f;
    for (int i = threadIdx.x; i < NPART; i += 256) s += g_partials[i];
    red[threadIdx.x] = s;
    __syncthreads();
#pragma unroll
    for (int k = 128; k; k >>= 1) {
        if (threadIdx.x < k) red[threadIdx.x] += red[threadIdx.x + k];
        __syncthreads();
    }
    if (threadIdx.x == 0 && out_size >= NZQ + NROWS + 1)
        out[NZQ + NROWS] = red[0] / (float)NZQ;
}

// ---------------------------------------------------------------------------
extern "C" void kernel_launch(void* const* d_in, const int* in_sizes, int n_in,
                              void* d_out, int out_size) {
    const float* z   = (const float*)d_in[0];
    const float* emb = (const float*)d_in[1];
    float* out = (float*)d_out;

    const int smemBytes =
        (TM * ZPITCH + TN * EPITCH) * 16 + (TN + TM) * 4;  // ~101.5 KB
    cudaFuncSetAttribute(vq_main, cudaFuncAttributeMaxDynamicSharedMemorySize,
                         smemBytes);

    // Defensive: zero the whole output (poisoned regions become deterministic)
    cudaMemsetAsync(d_out, 0, (size_t)out_size * sizeof(float));

    vq_init_best<<<(NROWS + 255) / 256, 256>>>();
    vq_esq<<<(K_CODES * 32 + 255) / 256, 256>>>(emb);

    dim3 grid(NROWS / TM, NSPLIT);   // 128 x 16 = 2048 CTAs
    vq_main<<<grid, 128, smemBytes>>>(z, emb);

    vq_gather<<<NPART, 256>>>(z, emb, out, out_size);
    vq_loss<<<1, 256>>>(out, out_size);
}

// round 3
// speedup vs baseline: 1.1101x; 1.1101x over previous
#include <cuda_runtime.h>
#include <math.h>

#define K_CODES 50257
#define D 144
#define CHUNKS 36            // D / 4
#define NROWS 4096
#define TM 32                // rows per CTA
#define TN 128               // codes per smem tile
#define EPITCH 40            // padded float4-chunks per e row (mult of 8 for swizzle)
#define ZPITCH 37            // float4-chunks per z row
#define NSPLIT 16
#define NTILES ((K_CODES + TN - 1) / TN)   // 393
#define NZQ (NROWS * D)                     // 589824
#define NPART (NZQ / 256)                   // 2304

__device__ unsigned long long g_best[NROWS];
__device__ float g_esq[K_CODES];
__device__ float g_partials[NPART];

// packed dual-FMA: acc(2xf32) += a(2xf32) * b(2xf32)
#define FMA_F32X2(acc, a, b) \
    asm("fma.rn.f32x2 %0, %1, %2, %0;" : "+l"(acc) : "l"(a), "l"(b))

// ---------------------------------------------------------------------------
// Kernel 0: init per-row argmin keys
// ---------------------------------------------------------------------------
__global__ void vq_init_best() {
    int i = blockIdx.x * blockDim.x + threadIdx.x;
    if (i < NROWS) g_best[i] = 0xFFFFFFFFFFFFFFFFull;
}

// ---------------------------------------------------------------------------
// Kernel 1: esq[k] = sum_d emb[k][d]^2   (one warp per code)
// (esq is ~2e-8; it vanishes against rowsq~144 in fp32, but keep exact.)
// ---------------------------------------------------------------------------
__global__ void vq_esq(const float* __restrict__ emb) {
    int warp = (blockIdx.x * blockDim.x + threadIdx.x) >> 5;
    int lane = threadIdx.x & 31;
    if (warp >= K_CODES) return;
    const float* row = emb + (size_t)warp * D;
    float s = 0.f;
    for (int d = lane; d < D; d += 32) {
        float v = row[d];
        s = fmaf(v, v, s);
    }
#pragma unroll
    for (int off = 16; off; off >>= 1)
        s += __shfl_xor_sync(0xffffffffu, s, off);
    if (lane == 0) g_esq[warp] = s;
}

// ---------------------------------------------------------------------------
// Kernel 2: main distance + argmin, packed f32x2 FMA inner loop
//   128 threads: warp = row-group (8 rows), lane = code-thread (4 codes)
// ---------------------------------------------------------------------------
__global__ void __launch_bounds__(128) vq_main(const float* __restrict__ z,
                                               const float* __restrict__ emb) {
    extern __shared__ float sm[];
    float4* zs4  = (float4*)sm;                        // [TM][ZPITCH]
    float4* es4  = zs4 + TM * ZPITCH;                  // [TN][EPITCH]
    float*  essq = (float*)(es4 + TN * EPITCH);        // [TN]
    float*  rowsq = essq + TN;                         // [TM]

    const int tid = threadIdx.x;
    const int ct  = tid & 31;   // lane: code-thread
    const int rt  = tid >> 5;   // warp: row-group
    const int rowBase = blockIdx.x * TM;

    // Load z tile (32 x 144 floats) as float4
    for (int f = tid; f < TM * CHUNKS; f += 128) {
        int r = f / CHUNKS, dc = f % CHUNKS;
        zs4[r * ZPITCH + dc] =
            ((const float4*)z)[(size_t)(rowBase + r) * CHUNKS + dc];
    }
    __syncthreads();

    // rowsq: sequential fp32 sum per row
    if (tid < TM) {
        const float* zr = (const float*)&zs4[tid * ZPITCH];
        float s = 0.f;
        for (int d = 0; d < D; d++) s = fmaf(zr[d], zr[d], s);
        rowsq[tid] = s;
    }

    float bestV[8];
    int   bestI[8];
#pragma unroll
    for (int r = 0; r < 8; r++) { bestV[r] = INFINITY; bestI[r] = 0; }

    const int tilesPerSplit = (NTILES + NSPLIT - 1) / NSPLIT;
    int tbeg = blockIdx.y * tilesPerSplit;
    int tend = tbeg + tilesPerSplit;
    if (tend > NTILES) tend = NTILES;

    for (int t = tbeg; t < tend; t++) {
        const int cb = t * TN;
        __syncthreads();   // protect es from previous tile's readers

        // Load e tile (128 codes x 36 chunks), XOR-swizzled
        for (int f = tid; f < TN * CHUNKS; f += 128) {
            int c = f / CHUNKS, dc = f % CHUNKS;
            int cg = cb + c;
            float4 v = make_float4(0.f, 0.f, 0.f, 0.f);
            if (cg < K_CODES)
                v = ((const float4*)emb)[(size_t)cg * CHUNKS + dc];
            es4[c * EPITCH + (dc ^ ((c >> 2) & 7))] = v;
        }
        if (tid < TN) {
            int cg = cb + tid;
            essq[tid] = (cg < K_CODES) ? g_esq[cg] : INFINITY;
        }
        __syncthreads();

        // Packed accumulators: each holds (sum of even comps, sum of odd comps)
        unsigned long long acc2[8][4];
#pragma unroll
        for (int r = 0; r < 8; r++)
#pragma unroll
            for (int j = 0; j < 4; j++) acc2[r][j] = 0ull;

#pragma unroll 2
        for (int dc = 0; dc < CHUNKS; dc++) {
            ulonglong2 ev2[4];
#pragma unroll
            for (int j = 0; j < 4; j++) {
                int c = ct * 4 + j;
                ev2[j] = *(const ulonglong2*)
                         &es4[c * EPITCH + (dc ^ ((c >> 2) & 7))];
            }
#pragma unroll
            for (int r = 0; r < 8; r++) {
                ulonglong2 zv2 = *(const ulonglong2*)
                                 &zs4[(rt * 8 + r) * ZPITCH + dc];
#pragma unroll
                for (int j = 0; j < 4; j++) {
                    FMA_F32X2(acc2[r][j], zv2.x, ev2[j].x);
                    FMA_F32X2(acc2[r][j], zv2.y, ev2[j].y);
                }
            }
        }

        // Epilogue: dot = lo + hi;  d = (rowsq + esq) - 2*dot
#pragma unroll
        for (int r = 0; r < 8; r++) {
            float rs = rowsq[rt * 8 + r];
#pragma unroll
            for (int j = 0; j < 4; j++) {
                int c = ct * 4 + j;
                unsigned long long v = acc2[r][j];
                float lo = __uint_as_float((unsigned)v);
                float hi = __uint_as_float((unsigned)(v >> 32));
                float dot = lo + hi;
                float d = (rs + essq[c]) - 2.0f * dot;
                if (d < bestV[r]) { bestV[r] = d; bestI[r] = cb + c; }
            }
        }
    }

    // Warp-reduce each row-group's best, tie -> smaller index via packed key
#pragma unroll
    for (int r = 0; r < 8; r++) {
        unsigned long long key =
            (((unsigned long long)__float_as_uint(bestV[r])) << 32) |
            (unsigned)bestI[r];
#pragma unroll
        for (int off = 16; off; off >>= 1) {
            unsigned long long o = __shfl_xor_sync(0xffffffffu, key, off);
            key = (o < key) ? o : key;
        }
        if (ct == 0) atomicMin(&g_best[rowBase + rt * 8 + r], key);
    }
}

// ---------------------------------------------------------------------------
// Kernel 3: gather z_q, write indices, per-block loss partials
// ---------------------------------------------------------------------------
__global__ void vq_gather(const float* __restrict__ z,
                          const float* __restrict__ emb,
                          float* __restrict__ out, int out_size) {
    __shared__ float red[256];
    int i = blockIdx.x * 256 + threadIdx.x;
    float dsq = 0.f;
    if (i < NZQ) {
        int row = i / D;
        int col = i - row * D;
        unsigned idx = (unsigned)(g_best[row] & 0xffffffffull);
        float q = emb[(size_t)idx * D + col];
        out[i] = q;
        float df = q - z[i];
        dsq = df * df;
        if (col == 0 && out_size >= NZQ + NROWS)
            out[NZQ + row] = (float)idx;
    }
    red[threadIdx.x] = dsq;
    __syncthreads();
#pragma unroll
    for (int s = 128; s; s >>= 1) {
        if (threadIdx.x < s) red[threadIdx.x] += red[threadIdx.x + s];
        __syncthreads();
    }
    if (threadIdx.x == 0) g_partials[blockIdx.x] = red[0];
}

// ---------------------------------------------------------------------------
// Kernel 4: final deterministic loss reduction
// ---------------------------------------------------------------------------
__global__ void vq_loss(float* __restrict__ out, int out_size) {
    __shared__ float red[256];
    float s = 0.f;
    for (int i = threadIdx.x; i < NPART; i += 256) s += g_partials[i];
    red[threadIdx.x] = s;
    __syncthreads();
#pragma unroll
    for (int k = 128; k; k >>= 1) {
        if (threadIdx.x < k) red[threadIdx.x] += red[threadIdx.x + k];
        __syncthreads();
    }
    if (threadIdx.x == 0 && out_size >= NZQ + NROWS + 1)
        out[NZQ + NROWS] = red[0] / (float)NZQ;
}

// ---------------------------------------------------------------------------
extern "C" void kernel_launch(void* const* d_in, const int* in_sizes, int n_in,
                              void* d_out, int out_size) {
    const float* z   = (const float*)d_in[0];
    const float* emb = (const float*)d_in[1];
    float* out = (float*)d_out;

    const int smemBytes =
        (TM * ZPITCH + TN * EPITCH) * 16 + (TN + TM) * 4;  // ~101.5 KB
    cudaFuncSetAttribute(vq_main, cudaFuncAttributeMaxDynamicSharedMemorySize,
                         smemBytes);

    cudaMemsetAsync(d_out, 0, (size_t)out_size * sizeof(float));

    vq_init_best<<<(NROWS + 255) / 256, 256>>>();
    vq_esq<<<(K_CODES * 32 + 255) / 256, 256>>>(emb);

    dim3 grid(NROWS / TM, NSPLIT);   // 128 x 16 = 2048 CTAs
    vq_main<<<grid, 128, smemBytes>>>(z, emb);

    vq_gather<<<NPART, 256>>>(z, emb, out, out_size);
    vq_loss<<<1, 256>>>(out, out_size);
}

// round 7
// speedup vs baseline: 2.6419x; 2.3799x over previous
#include <cuda_runtime.h>
#include <cuda_bf16.h>
#include <mma.h>
#include <math.h>
#include <stdint.h>

using namespace nvcuda;

#define K_CODES 50257
#define D 144
#define NROWS 4096
#define MT 128
#define NT 128
#define NKSTEP 9                            // 144 / 16
#define CTILES ((K_CODES + NT - 1) / NT)    // 393
#define RTILES (NROWS / MT)                 // 32
#define CAP 1024
#define MARGIN 1e-4f
#define NZQ (NROWS * D)
#define NPART (NZQ / 256)
#define SLD 152                             // smem ldm for A/B tiles (bf16)
#define CLD 132                             // smem ldm for C tile (f32)
#define AB_BYTES (MT * SLD * 2)             // 38912 per tile

__device__ __nv_bfloat16 g_zb[NROWS * D];
__device__ __nv_bfloat16 g_eb[K_CODES * D];
__device__ float g_esq[K_CODES];
__device__ float g_rowsq[NROWS];
__device__ unsigned g_min[NROWS];
__device__ unsigned g_cnt[NROWS];
__device__ unsigned g_cand[NROWS * CAP];
__device__ unsigned g_bestidx[NROWS];
__device__ float g_partials[NPART];

// ---------------------------------------------------------------------------
__global__ void vq_init() {
    int i = blockIdx.x * blockDim.x + threadIdx.x;
    if (i < NROWS) { g_min[i] = 0x7F800000u; g_cnt[i] = 0u; }
}

__global__ void vq_convert_z(const float* __restrict__ z) {
    int i = blockIdx.x * blockDim.x + threadIdx.x;
    if (i < NZQ) g_zb[i] = __float2bfloat16(z[i]);
}
__global__ void vq_convert_e(const float* __restrict__ emb) {
    int i = blockIdx.x * blockDim.x + threadIdx.x;
    if (i < K_CODES * D) g_eb[i] = __float2bfloat16(emb[i]);
}

__global__ void vq_esq(const float* __restrict__ emb) {
    int warp = (blockIdx.x * blockDim.x + threadIdx.x) >> 5;
    int lane = threadIdx.x & 31;
    if (warp >= K_CODES) return;
    const float* row = emb + (size_t)warp * D;
    float s = 0.f;
    for (int d = lane; d < D; d += 32) s = fmaf(row[d], row[d], s);
#pragma unroll
    for (int off = 16; off; off >>= 1) s += __shfl_xor_sync(~0u, s, off);
    if (lane == 0) g_esq[warp] = s;
}

__global__ void vq_rowsq(const float* __restrict__ z) {
    int r = blockIdx.x * blockDim.x + threadIdx.x;
    if (r >= NROWS) return;
    const float* zr = z + (size_t)r * D;
    float s = 0.f;
    for (int d = 0; d < D; d++) s = fmaf(zr[d], zr[d], s);
    g_rowsq[r] = s;
}

// ---------------------------------------------------------------------------
// Filter kernel: 128x128 bf16 wmma tile -> approx distances -> candidates
// ---------------------------------------------------------------------------
__global__ void __launch_bounds__(256) vq_mma() {
    extern __shared__ char sm[];
    __nv_bfloat16* As = (__nv_bfloat16*)sm;                // [128][SLD]
    __nv_bfloat16* Bs = (__nv_bfloat16*)(sm + AB_BYTES);   // [128][SLD]
    float*         Cs = (float*)sm;                         // [128][CLD], reused

    const int tid = threadIdx.x;
    const int wid = tid >> 5;
    const int rowBase  = blockIdx.x * MT;
    const int codeBase = blockIdx.y * NT;
    const int wm = wid >> 1;     // 0..3 : 32-row band
    const int wn = wid & 1;      // 0..1 : 64-code band

    // Stage A (z rows) and B (codes) into smem as 16B units (18 per row)
    for (int u = tid; u < MT * 18; u += 256) {
        int r = u / 18, c8 = (u % 18) * 8;
        *(uint4*)(As + r * SLD + c8) =
            *(const uint4*)(g_zb + (size_t)(rowBase + r) * D + c8);
    }
    for (int u = tid; u < NT * 18; u += 256) {
        int r = u / 18, c8 = (u % 18) * 8;
        uint4 v = make_uint4(0u, 0u, 0u, 0u);
        if (codeBase + r < K_CODES)
            v = *(const uint4*)(g_eb + (size_t)(codeBase + r) * D + c8);
        *(uint4*)(Bs + r * SLD + c8) = v;
    }
    __syncthreads();

    wmma::fragment<wmma::accumulator, 16, 16, 16, float> acc[2][4];
#pragma unroll
    for (int i = 0; i < 2; i++)
#pragma unroll
        for (int j = 0; j < 4; j++) wmma::fill_fragment(acc[i][j], 0.f);

#pragma unroll
    for (int ks = 0; ks < NKSTEP; ks++) {
        const int k = ks * 16;
        wmma::fragment<wmma::matrix_a, 16, 16, 16, __nv_bfloat16,
                       wmma::row_major> a[2];
        wmma::fragment<wmma::matrix_b, 16, 16, 16, __nv_bfloat16,
                       wmma::col_major> b[4];
#pragma unroll
        for (int i = 0; i < 2; i++)
            wmma::load_matrix_sync(a[i], As + (wm * 32 + i * 16) * SLD + k, SLD);
#pragma unroll
        for (int j = 0; j < 4; j++)
            wmma::load_matrix_sync(b[j], Bs + (wn * 64 + j * 16) * SLD + k, SLD);
#pragma unroll
        for (int i = 0; i < 2; i++)
#pragma unroll
            for (int j = 0; j < 4; j++)
                wmma::mma_sync(acc[i][j], a[i], b[j], acc[i][j]);
    }

    __syncthreads();   // A/B tiles dead; Cs overlays them
#pragma unroll
    for (int i = 0; i < 2; i++)
#pragma unroll
        for (int j = 0; j < 4; j++)
            wmma::store_matrix_sync(
                Cs + (wm * 32 + i * 16) * CLD + (wn * 64 + j * 16),
                acc[i][j], CLD, wmma::mem_row_major);
    __syncthreads();

    // Epilogue: 2 threads per row (halves of 64 codes each)
    const int rl   = tid >> 1;          // local row 0..127
    const int half = tid & 1;
    const int row  = rowBase + rl;
    const float rs = g_rowsq[row];

    float dmin = INFINITY;
#pragma unroll 8
    for (int j = 0; j < 64; j++) {
        int c = half * 64 + j;
        if (codeBase + c < K_CODES) {
            float d = rs - 2.0f * Cs[rl * CLD + c];
            dmin = fminf(dmin, d);
        }
    }
    dmin = fminf(dmin, __shfl_xor_sync(~0u, dmin, 1));
    unsigned old = (half == 0) ? atomicMin(&g_min[row], __float_as_uint(dmin))
                               : 0x7F800000u;
    old = __shfl_sync(~0u, old, (tid & 31) & ~1);
    float thr = fminf(__uint_as_float(old), dmin) + MARGIN;

#pragma unroll 8
    for (int j = 0; j < 64; j++) {
        int c = half * 64 + j;
        int code = codeBase + c;
        if (code < K_CODES) {
            float d = rs - 2.0f * Cs[rl * CLD + c];
            if (d <= thr) {
                unsigned slot = atomicAdd(&g_cnt[row], 1u);
                if (slot < CAP) g_cand[(size_t)row * CAP + slot] = (unsigned)code;
            }
        }
    }
}

// ---------------------------------------------------------------------------
// Exact refine: recompute candidates with R2's bit-exact fp32 arithmetic
// ---------------------------------------------------------------------------
__global__ void __launch_bounds__(128) vq_refine(const float* __restrict__ z,
                                                 const float* __restrict__ emb) {
    __shared__ float zr[D];
    __shared__ float s_rs;
    __shared__ unsigned long long red[128];
    const int row = blockIdx.x;
    const int tid = threadIdx.x;

    for (int d = tid; d < D; d += 128) zr[d] = z[(size_t)row * D + d];
    __syncthreads();
    if (tid == 0) {
        float s = 0.f;
        for (int d = 0; d < D; d++) s = fmaf(zr[d], zr[d], s);
        s_rs = s;
    }
    __syncthreads();
    const float rs = s_rs;

    unsigned cnt = g_cnt[row];
    unsigned long long best = 0xFFFFFFFFFFFFFFFFull;

    if (cnt <= CAP) {
        for (unsigned i = tid; i < cnt; i += 128) {
            unsigned idx = g_cand[(size_t)row * CAP + i];
            const float* er = emb + (size_t)idx * D;
            float dot = 0.f;
            for (int d = 0; d < D; d++) dot = fmaf(zr[d], er[d], dot);
            float dv = (rs + g_esq[idx]) - 2.0f * dot;
            unsigned long long key =
                (((unsigned long long)__float_as_uint(dv)) << 32) | idx;
            if (key < best) best = key;
        }
    } else {  // overflow fallback: exact full scan (still deterministic)
        for (unsigned idx = tid; idx < K_CODES; idx += 128) {
            const float* er = emb + (size_t)idx * D;
            float dot = 0.f;
            for (int d = 0; d < D; d++) dot = fmaf(zr[d], er[d], dot);
            float dv = (rs + g_esq[idx]) - 2.0f * dot;
            unsigned long long key =
                (((unsigned long long)__float_as_uint(dv)) << 32) | idx;
            if (key < best) best = key;
        }
    }
    red[tid] = best;
    __syncthreads();
#pragma unroll
    for (int s = 64; s; s >>= 1) {
        if (tid < s && red[tid + s] < red[tid]) red[tid] = red[tid + s];
        __syncthreads();
    }
    if (tid == 0) g_bestidx[row] = (unsigned)(red[0] & 0xFFFFFFFFull);
}

// ---------------------------------------------------------------------------
__global__ void vq_gather(const float* __restrict__ z,
                          const float* __restrict__ emb,
                          float* __restrict__ out, int out_size) {
    __shared__ float red[256];
    int i = blockIdx.x * 256 + threadIdx.x;
    float dsq = 0.f;
    if (i < NZQ) {
        int row = i / D;
        int col = i - row * D;
        unsigned idx = g_bestidx[row];
        float q = emb[(size_t)idx * D + col];
        out[i] = q;
        float df = q - z[i];
        dsq = df * df;
        if (col == 0 && out_size >= NZQ + NROWS)
            out[NZQ + row] = (float)idx;
    }
    red[threadIdx.x] = dsq;
    __syncthreads();
#pragma unroll
    for (int s = 128; s; s >>= 1) {
        if (threadIdx.x < s) red[threadIdx.x] += red[threadIdx.x + s];
        __syncthreads();
    }
    if (threadIdx.x == 0) g_partials[blockIdx.x] = red[0];
}

__global__ void vq_loss(float* __restrict__ out, int out_size) {
    __shared__ float red[256];
    float s = 0.f;
    for (int i = threadIdx.x; i < NPART; i += 256) s += g_partials[i];
    red[threadIdx.x] = s;
    __syncthreads();
#pragma unroll
    for (int k = 128; k; k >>= 1) {
        if (threadIdx.x < k) red[threadIdx.x] += red[threadIdx.x + k];
        __syncthreads();
    }
    if (threadIdx.x == 0 && out_size >= NZQ + NROWS + 1)
        out[NZQ + NROWS] = red[0] / (float)NZQ;
}

// ---------------------------------------------------------------------------
extern "C" void kernel_launch(void* const* d_in, const int* in_sizes, int n_in,
                              void* d_out, int out_size) {
    const float* z   = (const float*)d_in[0];
    const float* emb = (const float*)d_in[1];
    float* out = (float*)d_out;

    const int smemBytes = 2 * AB_BYTES;   // 77824 (C tile overlays)
    cudaFuncSetAttribute(vq_mma, cudaFuncAttributeMaxDynamicSharedMemorySize,
                         smemBytes);

    cudaMemsetAsync(d_out, 0, (size_t)out_size * sizeof(float));

    vq_init<<<(NROWS + 255) / 256, 256>>>();
    vq_convert_z<<<(NZQ + 255) / 256, 256>>>(z);
    vq_convert_e<<<(K_CODES * D + 255) / 256, 256>>>(emb);
    vq_esq<<<(K_CODES * 32 + 255) / 256, 256>>>(emb);
    vq_rowsq<<<(NROWS + 255) / 256, 256>>>(z);

    dim3 grid(RTILES, CTILES);   // 32 x 393
    vq_mma<<<grid, 256, smemBytes>>>();

    vq_refine<<<NROWS, 128>>>(z, emb);
    vq_gather<<<NPART, 256>>>(z, emb, out, out_size);
    vq_loss<<<1, 256>>>(out, out_size);
}